// round 5
// baseline (speedup 1.0000x reference)
#include <cuda_runtime.h>
#include <cuda_bf16.h>
#include <cstdint>
#include <cstddef>

// ---------------- problem constants ----------------
#define NTOK   8192      // 2 * 4096 tokens
#define ORIGF  4096
#define ACT    2048
#define RANKLB 16

// ---------------- GEMM tiling ----------------
#define TM 128
#define TN 128
#define NCHUNK 96        // 3 segments * (2048/64) chunks of K=64 bf16 (128B rows)
#define NST 3

#define A_STAGE_BYTES (TM*128)                       // 16 KB
#define STAGE_BYTES   (2*TM*128)                     // 32 KB (A+B)
#define GEMM_SMEM     (NST*STAGE_BYTES)              // 96 KB

// ---------------- scratch (allocation-free: __device__ globals) ----------------
__device__ __align__(256) __nv_bfloat16 g_xhi[(size_t)NTOK*ACT];
__device__ __align__(256) __nv_bfloat16 g_xlo[(size_t)NTOK*ACT];
__device__ __align__(256) __nv_bfloat16 g_whi[(size_t)ACT*ACT];
__device__ __align__(256) __nv_bfloat16 g_wlo[(size_t)ACT*ACT];
__device__ __align__(256) float         g_comb[(size_t)NTOK*ACT];
__device__ int g_inv[ORIGF];

// ---------------- PTX helpers ----------------
__device__ __forceinline__ uint32_t smem_u32(const void* p) {
    uint32_t a;
    asm("{ .reg .u64 t; cvta.to.shared.u64 t, %1; cvt.u32.u64 %0, t; }"
        : "=r"(a) : "l"(p));
    return a;
}
#define SWZ(o) ((uint32_t)(o) ^ ((((uint32_t)(o)) >> 3) & 0x70u))

__device__ __forceinline__ void ldsm4(uint32_t* r, uint32_t addr) {
    asm volatile("ldmatrix.sync.aligned.m8n8.x4.shared.b16 {%0,%1,%2,%3}, [%4];"
                 : "=r"(r[0]), "=r"(r[1]), "=r"(r[2]), "=r"(r[3])
                 : "r"(addr));
}

__device__ __forceinline__ void mma16816(float* c, const uint32_t* a, const uint32_t* b) {
    asm volatile(
        "mma.sync.aligned.m16n8k16.row.col.f32.bf16.bf16.f32 "
        "{%0,%1,%2,%3}, {%4,%5,%6,%7}, {%8,%9}, {%0,%1,%2,%3};"
        : "+f"(c[0]), "+f"(c[1]), "+f"(c[2]), "+f"(c[3])
        : "r"(a[0]), "r"(a[1]), "r"(a[2]), "r"(a[3]), "r"(b[0]), "r"(b[1]));
}

// Both tiles 128 rows x 128B; 256 threads * 8 granules of 16B each.
__device__ __forceinline__ void issue_loads(uint32_t sA, uint32_t sB,
                                            const char* Ab, const char* Bb,
                                            int m0, int n0, uint32_t koff, int tid) {
    const int c  = tid & 7;        // 16B chunk within 128B row
    const int r0 = tid >> 3;       // base row (0..31)
    #pragma unroll
    for (int t = 0; t < 4; t++) {
        int r = r0 + t * 32;
        uint32_t so = SWZ((uint32_t)r * 128u + (uint32_t)c * 16u);
        const char* g = Ab + ((size_t)(m0 + r)) * (ACT * 2) + koff + (size_t)c * 16;
        asm volatile("cp.async.cg.shared.global [%0], [%1], 16;\n"
                     :: "r"(sA + so), "l"(g) : "memory");
    }
    #pragma unroll
    for (int t = 0; t < 4; t++) {
        int r = r0 + t * 32;
        uint32_t so = SWZ((uint32_t)r * 128u + (uint32_t)c * 16u);
        const char* g = Bb + ((size_t)(n0 + r)) * (ACT * 2) + koff + (size_t)c * 16;
        asm volatile("cp.async.cg.shared.global [%0], [%1], 16;\n"
                     :: "r"(sB + so), "l"(g) : "memory");
    }
}

// ---------------- kernel 1: W_eff = W + 2*loraB@loraA, split to bf16 hi/lo ----------------
__global__ void prep_w_kernel(const float* __restrict__ Wb,
                              const float* __restrict__ lA,
                              const float* __restrict__ lB) {
    __shared__ float lb[16][16];
    int ob = blockIdx.x * 16;
    {
        int o = threadIdx.x >> 4, r = threadIdx.x & 15;
        lb[o][r] = 2.0f * lB[(size_t)(ob + o) * RANKLB + r];
    }
    __syncthreads();
    for (int a = threadIdx.x; a < ACT; a += 256) {
        float av[16];
        #pragma unroll
        for (int r = 0; r < 16; r++) av[r] = lA[(size_t)r * ACT + a];
        #pragma unroll
        for (int o = 0; o < 16; o++) {
            float acc = Wb[(size_t)(ob + o) * ACT + a];
            #pragma unroll
            for (int r = 0; r < 16; r++) acc += lb[o][r] * av[r];
            __nv_bfloat16 h = __float2bfloat16(acc);
            g_whi[(size_t)(ob + o) * ACT + a] = h;
            g_wlo[(size_t)(ob + o) * ACT + a] =
                __float2bfloat16(acc - __bfloat162float(h));
        }
    }
}

// ---------------- kernel 2: gather active in-features, split to bf16 hi/lo ----------------
__global__ void gather_x_kernel(const float* __restrict__ x,
                                const int* __restrict__ in_idx) {
    int n = blockIdx.y;
    int a = blockIdx.x * blockDim.x + threadIdx.x;
    int idx = in_idx[a];
    float v = x[(size_t)n * ORIGF + idx];
    __nv_bfloat16 h = __float2bfloat16(v);
    g_xhi[(size_t)n * ACT + a] = h;
    g_xlo[(size_t)n * ACT + a] = __float2bfloat16(v - __bfloat162float(h));
}

// ---------------- kernel 3: inverse out-index map via binary search ----------------
__global__ void build_inv_kernel(const int* __restrict__ out_idx) {
    int j = blockIdx.x * blockDim.x + threadIdx.x;
    if (j >= ORIGF) return;
    int lo = 0, hi = ACT;
    while (lo < hi) { int mid = (lo + hi) >> 1; if (out_idx[mid] < j) lo = mid + 1; else hi = mid; }
    g_inv[j] = (lo < ACT && out_idx[lo] == j) ? lo : -1;
}

// ---------------- kernel 4: HMMA GEMM (3-term bf16 split, fp32 accum) ----------------
// C[m,n] = sum_k A[m,k]*B[n,k]  (B row = output feature, k-contiguous => "col" operand)
__global__ void __launch_bounds__(256, 2) gemm_kernel() {
    extern __shared__ char smem[];
    const uint32_t sbase = smem_u32(smem);
    const int tid  = threadIdx.x;
    const int wid  = tid >> 5;
    const int lane = tid & 31;
    const int m0 = blockIdx.y * TM;
    const int n0 = blockIdx.x * TN;
    const int wm = (wid & 1) * 64;     // warp M offset within tile
    const int wn = (wid >> 1) * 32;    // warp N offset within tile

    // Per-lane ldmatrix base addresses (kstep 0), swizzled.
    // kstep advance is a pure XOR: addr_k = addr_0 ^ (ks*32).
    uint32_t a_addr[4], b_addr[2];
    {
        int lr = (lane & 7) + 8 * ((lane >> 3) & 1);
        int lk = ((lane >> 4) & 1) * 16;
        #pragma unroll
        for (int i = 0; i < 4; i++) {
            uint32_t row = (uint32_t)(wm + i * 16 + lr);
            a_addr[i] = SWZ(row * 128u + (uint32_t)lk);
        }
        int br = (lane & 7) + 8 * ((lane >> 4) & 1);
        int bk = ((lane >> 3) & 1) * 16;
        #pragma unroll
        for (int j2 = 0; j2 < 2; j2++) {
            uint32_t row = (uint32_t)(wn + j2 * 16 + br);
            b_addr[j2] = SWZ(row * 128u + (uint32_t)bk);
        }
    }

    float acc[4][4][4];
    #pragma unroll
    for (int i = 0; i < 4; i++)
        #pragma unroll
        for (int j = 0; j < 4; j++)
            #pragma unroll
            for (int r = 0; r < 4; r++) acc[i][j][r] = 0.0f;

    // prologue: chunks 0..2 (all segment 0: xhi * whi)
    #pragma unroll
    for (int k = 0; k < NST; k++) {
        uint32_t st = sbase + k * STAGE_BYTES;
        issue_loads(st, st + A_STAGE_BYTES,
                    (const char*)g_xhi, (const char*)g_whi,
                    m0, n0, (uint32_t)k * 128u, tid);
        asm volatile("cp.async.commit_group;" ::: "memory");
    }

    int s = 0;
    for (int k = 0; k < NCHUNK; k++) {
        asm volatile("cp.async.wait_group 2;" ::: "memory");
        __syncthreads();

        const uint32_t sa = sbase + s * STAGE_BYTES;
        const uint32_t sb = sa + A_STAGE_BYTES;
        #pragma unroll
        for (int ks = 0; ks < 4; ks++) {
            const uint32_t kb = (uint32_t)ks * 32u;
            uint32_t a[4][4], b[2][4];
            #pragma unroll
            for (int i = 0; i < 4; i++)  ldsm4(a[i],  sa + (a_addr[i]  ^ kb));
            #pragma unroll
            for (int j2 = 0; j2 < 2; j2++) ldsm4(b[j2], sb + (b_addr[j2] ^ kb));
            #pragma unroll
            for (int i = 0; i < 4; i++)
                #pragma unroll
                for (int j = 0; j < 4; j++)
                    mma16816(acc[i][j], a[i], &b[j >> 1][(j & 1) * 2]);
        }
        __syncthreads();   // all warps done reading stage s

        int kn = k + NST;
        if (kn < NCHUNK) {
            int seg = kn >> 5;   // 0: hi*hi, 1: lo*hi, 2: hi*lo
            const char* Ab = (seg == 1) ? (const char*)g_xlo : (const char*)g_xhi;
            const char* Bb = (seg == 2) ? (const char*)g_wlo : (const char*)g_whi;
            uint32_t st = sbase + s * STAGE_BYTES;
            issue_loads(st, st + A_STAGE_BYTES, Ab, Bb,
                        m0, n0, (uint32_t)(kn & 31) * 128u, tid);
        }
        asm volatile("cp.async.commit_group;" ::: "memory");  // empty group at tail keeps wait_group 2 correct

        s = (s == NST - 1) ? 0 : s + 1;
    }

    // epilogue: acc -> g_comb
    #pragma unroll
    for (int i = 0; i < 4; i++) {
        int mrow = m0 + wm + i * 16 + (lane >> 2);
        float* d0 = g_comb + (size_t)mrow * ACT + n0 + wn;
        float* d1 = d0 + (size_t)8 * ACT;
        #pragma unroll
        for (int j = 0; j < 4; j++) {
            int nc = j * 8 + (lane & 3) * 2;
            float2 v0; v0.x = acc[i][j][0]; v0.y = acc[i][j][1];
            float2 v1; v1.x = acc[i][j][2]; v1.y = acc[i][j][3];
            *reinterpret_cast<float2*>(d0 + nc) = v0;
            *reinterpret_cast<float2*>(d1 + nc) = v1;
        }
    }
}

// ---------------- kernel 5: expand to full 4096-wide output (+bias, zeros) ----------------
__global__ void expand_out_kernel(float* __restrict__ out,
                                  const float* __restrict__ bias) {
    int n = blockIdx.y;
    int j = blockIdx.x * blockDim.x + threadIdx.x;
    int iv = g_inv[j];
    float v = 0.0f;
    if (iv >= 0) v = g_comb[(size_t)n * ACT + iv] + bias[iv];
    out[(size_t)n * ORIGF + j] = v;
}

// ---------------- launch ----------------
extern "C" void kernel_launch(void* const* d_in, const int* in_sizes, int n_in,
                              void* d_out, int out_size) {
    (void)in_sizes; (void)n_in; (void)out_size;
    const float* x    = (const float*)d_in[0];
    const float* Wb   = (const float*)d_in[1];
    const float* bb   = (const float*)d_in[2];
    const float* lA   = (const float*)d_in[3];
    const float* lB   = (const float*)d_in[4];
    const int*   iin  = (const int*)d_in[5];
    const int*   iout = (const int*)d_in[6];
    float* out = (float*)d_out;

    cudaFuncSetAttribute(gemm_kernel,
                         cudaFuncAttributeMaxDynamicSharedMemorySize, GEMM_SMEM);

    prep_w_kernel<<<ACT / 16, 256>>>(Wb, lA, lB);
    gather_x_kernel<<<dim3(ACT / 256, NTOK), 256>>>(x, iin);
    build_inv_kernel<<<ORIGF / 256, 256>>>(iout);
    gemm_kernel<<<dim3(ACT / TN, NTOK / TM), 256, GEMM_SMEM>>>();
    expand_out_kernel<<<dim3(ORIGF / 256, NTOK), 256>>>(out, bb);
}

// round 7
// speedup vs baseline: 2.2190x; 2.2190x over previous
#include <cuda_runtime.h>
#include <cuda_fp16.h>
#include <cstdint>
#include <cstddef>

// ---------------- problem constants ----------------
#define NTOK   8192      // 2 * 4096 tokens
#define ORIGF  4096
#define ACT    2048
#define RANKLB 16

// ---------------- GEMM tiling ----------------
#define TM 128
#define TN 128
#define NCHUNK 32        // single fp16 segment: 2048/64 chunks of K=64 (128B rows)
#define NST 3

#define A_STAGE_BYTES (TM*128)                       // 16 KB
#define STAGE_BYTES   (2*TM*128)                     // 32 KB (A+B)
#define GEMM_SMEM     (NST*STAGE_BYTES)              // 96 KB

// ---------------- scratch (allocation-free: __device__ globals) ----------------
__device__ __align__(256) __half g_xh[(size_t)NTOK*ACT];
__device__ __align__(256) __half g_wh[(size_t)ACT*ACT];

// ---------------- PTX helpers ----------------
__device__ __forceinline__ uint32_t smem_u32(const void* p) {
    uint32_t a;
    asm("{ .reg .u64 t; cvta.to.shared.u64 t, %1; cvt.u32.u64 %0, t; }"
        : "=r"(a) : "l"(p));
    return a;
}
#define SWZ(o) ((uint32_t)(o) ^ ((((uint32_t)(o)) >> 3) & 0x70u))

__device__ __forceinline__ void ldsm4(uint32_t* r, uint32_t addr) {
    asm volatile("ldmatrix.sync.aligned.m8n8.x4.shared.b16 {%0,%1,%2,%3}, [%4];"
                 : "=r"(r[0]), "=r"(r[1]), "=r"(r[2]), "=r"(r[3])
                 : "r"(addr));
}

__device__ __forceinline__ void mma16816(float* c, const uint32_t* a, const uint32_t* b) {
    asm volatile(
        "mma.sync.aligned.m16n8k16.row.col.f32.f16.f16.f32 "
        "{%0,%1,%2,%3}, {%4,%5,%6,%7}, {%8,%9}, {%0,%1,%2,%3};"
        : "+f"(c[0]), "+f"(c[1]), "+f"(c[2]), "+f"(c[3])
        : "r"(a[0]), "r"(a[1]), "r"(a[2]), "r"(a[3]), "r"(b[0]), "r"(b[1]));
}

// Both tiles 128 rows x 128B; 256 threads * 8 granules of 16B each.
__device__ __forceinline__ void issue_loads(uint32_t sA, uint32_t sB,
                                            int m0, int n0, uint32_t koff, int tid) {
    const int c  = tid & 7;        // 16B chunk within 128B row
    const int r0 = tid >> 3;       // base row (0..31)
    const char* Ab = (const char*)g_xh;
    const char* Bb = (const char*)g_wh;
    #pragma unroll
    for (int t = 0; t < 4; t++) {
        int r = r0 + t * 32;
        uint32_t so = SWZ((uint32_t)r * 128u + (uint32_t)c * 16u);
        const char* g = Ab + ((size_t)(m0 + r)) * (ACT * 2) + koff + (size_t)c * 16;
        asm volatile("cp.async.cg.shared.global [%0], [%1], 16;\n"
                     :: "r"(sA + so), "l"(g) : "memory");
    }
    #pragma unroll
    for (int t = 0; t < 4; t++) {
        int r = r0 + t * 32;
        uint32_t so = SWZ((uint32_t)r * 128u + (uint32_t)c * 16u);
        const char* g = Bb + ((size_t)(n0 + r)) * (ACT * 2) + koff + (size_t)c * 16;
        asm volatile("cp.async.cg.shared.global [%0], [%1], 16;\n"
                     :: "r"(sB + so), "l"(g) : "memory");
    }
}

// ---------------- kernel 1: W_eff = W + 2*loraB@loraA -> fp16 ----------------
__global__ void prep_w_kernel(const float* __restrict__ Wb,
                              const float* __restrict__ lA,
                              const float* __restrict__ lB) {
    __shared__ float lb[16][16];
    int ob = blockIdx.x * 16;
    {
        int o = threadIdx.x >> 4, r = threadIdx.x & 15;
        lb[o][r] = 2.0f * lB[(size_t)(ob + o) * RANKLB + r];
    }
    __syncthreads();
    for (int a = threadIdx.x; a < ACT; a += 256) {
        float av[16];
        #pragma unroll
        for (int r = 0; r < 16; r++) av[r] = lA[(size_t)r * ACT + a];
        #pragma unroll
        for (int o = 0; o < 16; o++) {
            float acc = Wb[(size_t)(ob + o) * ACT + a];
            #pragma unroll
            for (int r = 0; r < 16; r++) acc += lb[o][r] * av[r];
            g_wh[(size_t)(ob + o) * ACT + a] = __float2half_rn(acc);
        }
    }
}

// ---------------- kernel 2: gather active in-features -> fp16 (half2 stores) ----
__global__ void gather_x_kernel(const float* __restrict__ x,
                                const int* __restrict__ in_idx) {
    int n = blockIdx.y;
    int a = (blockIdx.x * blockDim.x + threadIdx.x) * 2;
    int i0 = in_idx[a];
    int i1 = in_idx[a + 1];
    const float* xr = x + (size_t)n * ORIGF;
    __half2 v = __floats2half2_rn(xr[i0], xr[i1]);
    *reinterpret_cast<__half2*>(&g_xh[(size_t)n * ACT + a]) = v;
}

// ---------------- kernel 3: zero-fill the full output ----------------
__global__ void zero_out_kernel(float4* __restrict__ out, size_t n4) {
    size_t stride = (size_t)gridDim.x * blockDim.x;
    for (size_t i = (size_t)blockIdx.x * blockDim.x + threadIdx.x; i < n4; i += stride)
        out[i] = make_float4(0.f, 0.f, 0.f, 0.f);
}

// ---------------- kernel 4: fp16 HMMA GEMM + fused bias/scatter epilogue ----
// C[m,n] = sum_k A[m,k]*B[n,k]; store C[m,n]+bias[n] at out[m, out_idx[n]]
__global__ void __launch_bounds__(256, 2) gemm_kernel(float* __restrict__ out,
                                                      const float* __restrict__ bias,
                                                      const int* __restrict__ oidx) {
    extern __shared__ char smem[];
    const uint32_t sbase = smem_u32(smem);
    const int tid  = threadIdx.x;
    const int wid  = tid >> 5;
    const int lane = tid & 31;
    const int m0 = blockIdx.y * TM;
    const int n0 = blockIdx.x * TN;
    const int wm = (wid & 1) * 64;     // warp M offset within tile
    const int wn = (wid >> 1) * 32;    // warp N offset within tile

    // Per-lane ldmatrix base addresses (kstep 0), swizzled.
    // kstep advance is a pure XOR: addr_k = addr_0 ^ (ks*32).
    uint32_t a_addr[4], b_addr[2];
    {
        int lr = (lane & 7) + 8 * ((lane >> 3) & 1);
        int lk = ((lane >> 4) & 1) * 16;
        #pragma unroll
        for (int i = 0; i < 4; i++) {
            uint32_t row = (uint32_t)(wm + i * 16 + lr);
            a_addr[i] = SWZ(row * 128u + (uint32_t)lk);
        }
        int br = (lane & 7) + 8 * ((lane >> 4) & 1);
        int bk = ((lane >> 3) & 1) * 16;
        #pragma unroll
        for (int j2 = 0; j2 < 2; j2++) {
            uint32_t row = (uint32_t)(wn + j2 * 16 + br);
            b_addr[j2] = SWZ(row * 128u + (uint32_t)bk);
        }
    }

    float acc[4][4][4];
    #pragma unroll
    for (int i = 0; i < 4; i++)
        #pragma unroll
        for (int j = 0; j < 4; j++)
            #pragma unroll
            for (int r = 0; r < 4; r++) acc[i][j][r] = 0.0f;

    // prologue
    #pragma unroll
    for (int k = 0; k < NST; k++) {
        uint32_t st = sbase + k * STAGE_BYTES;
        issue_loads(st, st + A_STAGE_BYTES, m0, n0, (uint32_t)k * 128u, tid);
        asm volatile("cp.async.commit_group;" ::: "memory");
    }

    int s = 0;
    for (int k = 0; k < NCHUNK; k++) {
        asm volatile("cp.async.wait_group 2;" ::: "memory");
        __syncthreads();

        const uint32_t sa = sbase + s * STAGE_BYTES;
        const uint32_t sb = sa + A_STAGE_BYTES;
        #pragma unroll
        for (int ks = 0; ks < 4; ks++) {
            const uint32_t kb = (uint32_t)ks * 32u;
            uint32_t a[4][4], b[2][4];
            #pragma unroll
            for (int i = 0; i < 4; i++)  ldsm4(a[i],  sa + (a_addr[i]  ^ kb));
            #pragma unroll
            for (int j2 = 0; j2 < 2; j2++) ldsm4(b[j2], sb + (b_addr[j2] ^ kb));
            #pragma unroll
            for (int i = 0; i < 4; i++)
                #pragma unroll
                for (int j = 0; j < 4; j++)
                    mma16816(acc[i][j], a[i], &b[j >> 1][(j & 1) * 2]);
        }
        __syncthreads();   // all warps done reading stage s

        int kn = k + NST;
        if (kn < NCHUNK) {
            uint32_t st = sbase + s * STAGE_BYTES;
            issue_loads(st, st + A_STAGE_BYTES, m0, n0, (uint32_t)kn * 128u, tid);
        }
        asm volatile("cp.async.commit_group;" ::: "memory");  // empty group at tail keeps wait_group 2 correct

        s = (s == NST - 1) ? 0 : s + 1;
    }

    // epilogue: fused bias + scatter into final out
    int   cc[4][2];
    float bb2[4][2];
    #pragma unroll
    for (int j = 0; j < 4; j++) {
        int nc = n0 + wn + j * 8 + (lane & 3) * 2;
        cc[j][0]  = oidx[nc];     cc[j][1]  = oidx[nc + 1];
        bb2[j][0] = bias[nc];     bb2[j][1] = bias[nc + 1];
    }
    #pragma unroll
    for (int i = 0; i < 4; i++) {
        int mrow = m0 + wm + i * 16 + (lane >> 2);
        float* r0 = out + (size_t)mrow * ORIGF;
        float* r1 = r0 + (size_t)8 * ORIGF;
        #pragma unroll
        for (int j = 0; j < 4; j++) {
            r0[cc[j][0]] = acc[i][j][0] + bb2[j][0];
            r0[cc[j][1]] = acc[i][j][1] + bb2[j][1];
            r1[cc[j][0]] = acc[i][j][2] + bb2[j][0];
            r1[cc[j][1]] = acc[i][j][3] + bb2[j][1];
        }
    }
}

// ---------------- launch ----------------
extern "C" void kernel_launch(void* const* d_in, const int* in_sizes, int n_in,
                              void* d_out, int out_size) {
    (void)in_sizes; (void)n_in; (void)out_size;
    const float* x    = (const float*)d_in[0];
    const float* Wb   = (const float*)d_in[1];
    const float* bb   = (const float*)d_in[2];
    const float* lA   = (const float*)d_in[3];
    const float* lB   = (const float*)d_in[4];
    const int*   iin  = (const int*)d_in[5];
    const int*   iout = (const int*)d_in[6];
    float* out = (float*)d_out;

    cudaFuncSetAttribute(gemm_kernel,
                         cudaFuncAttributeMaxDynamicSharedMemorySize, GEMM_SMEM);

    zero_out_kernel<<<2048, 256>>>((float4*)out, (size_t)NTOK * ORIGF / 4);
    prep_w_kernel<<<ACT / 16, 256>>>(Wb, lA, lB);
    gather_x_kernel<<<dim3(ACT / 512, NTOK), 256>>>(x, iin);
    gemm_kernel<<<dim3(ACT / TN, NTOK / TM), 256, GEMM_SMEM>>>(out, bb, iout);
}

// round 9
// speedup vs baseline: 2.2943x; 1.0339x over previous
#include <cuda_runtime.h>
#include <cuda_fp16.h>
#include <cstdint>
#include <cstddef>

// ---------------- problem constants ----------------
#define NTOK   8192      // 2 * 4096 tokens
#define ORIGF  4096
#define ACT    2048
#define RANKLB 16

// ---------------- GEMM tiling ----------------
#define TM 128
#define TN 128
#define NCHUNK 32        // single fp16 segment: 2048/64 chunks of K=64 (128B rows)
#define NST 3

#define A_STAGE_BYTES (TM*128)                       // 16 KB
#define STAGE_BYTES   (2*TM*128)                     // 32 KB (A+B)
#define GEMM_SMEM     (NST*STAGE_BYTES)              // 96 KB

// ---------------- scratch (allocation-free: __device__ globals) ----------------
__device__ __align__(256) __half g_xh[(size_t)NTOK*ACT];
__device__ __align__(256) __half g_wh[(size_t)ACT*ACT];
__device__ int g_ninv[ACT];    // compact list of the 2048 INACTIVE output columns

// ---------------- PTX helpers ----------------
__device__ __forceinline__ uint32_t smem_u32(const void* p) {
    uint32_t a;
    asm("{ .reg .u64 t; cvta.to.shared.u64 t, %1; cvt.u32.u64 %0, t; }"
        : "=r"(a) : "l"(p));
    return a;
}
#define SWZ(o) ((uint32_t)(o) ^ ((((uint32_t)(o)) >> 3) & 0x70u))

__device__ __forceinline__ void ldsm4(uint32_t* r, uint32_t addr) {
    asm volatile("ldmatrix.sync.aligned.m8n8.x4.shared.b16 {%0,%1,%2,%3}, [%4];"
                 : "=r"(r[0]), "=r"(r[1]), "=r"(r[2]), "=r"(r[3])
                 : "r"(addr));
}

__device__ __forceinline__ void mma16816(float* c, const uint32_t* a, const uint32_t* b) {
    asm volatile(
        "mma.sync.aligned.m16n8k16.row.col.f32.f16.f16.f32 "
        "{%0,%1,%2,%3}, {%4,%5,%6,%7}, {%8,%9}, {%0,%1,%2,%3};"
        : "+f"(c[0]), "+f"(c[1]), "+f"(c[2]), "+f"(c[3])
        : "r"(a[0]), "r"(a[1]), "r"(a[2]), "r"(a[3]), "r"(b[0]), "r"(b[1]));
}

// Both tiles 128 rows x 128B; 256 threads * 8 granules of 16B each.
__device__ __forceinline__ void issue_loads(uint32_t sA, uint32_t sB,
                                            int m0, int n0, uint32_t koff, int tid) {
    const int c  = tid & 7;        // 16B chunk within 128B row
    const int r0 = tid >> 3;       // base row (0..31)
    const char* Ab = (const char*)g_xh;
    const char* Bb = (const char*)g_wh;
    #pragma unroll
    for (int t = 0; t < 4; t++) {
        int r = r0 + t * 32;
        uint32_t so = SWZ((uint32_t)r * 128u + (uint32_t)c * 16u);
        const char* g = Ab + ((size_t)(m0 + r)) * (ACT * 2) + koff + (size_t)c * 16;
        asm volatile("cp.async.cg.shared.global [%0], [%1], 16;\n"
                     :: "r"(sA + so), "l"(g) : "memory");
    }
    #pragma unroll
    for (int t = 0; t < 4; t++) {
        int r = r0 + t * 32;
        uint32_t so = SWZ((uint32_t)r * 128u + (uint32_t)c * 16u);
        const char* g = Bb + ((size_t)(n0 + r)) * (ACT * 2) + koff + (size_t)c * 16;
        asm volatile("cp.async.cg.shared.global [%0], [%1], 16;\n"
                     :: "r"(sB + so), "l"(g) : "memory");
    }
}

// ---------------- kernel 1: W_eff = W + 2*loraB@loraA -> fp16 ----------------
__global__ void prep_w_kernel(const float* __restrict__ Wb,
                              const float* __restrict__ lA,
                              const float* __restrict__ lB) {
    __shared__ float lb[16][16];
    int ob = blockIdx.x * 16;
    {
        int o = threadIdx.x >> 4, r = threadIdx.x & 15;
        lb[o][r] = 2.0f * lB[(size_t)(ob + o) * RANKLB + r];
    }
    __syncthreads();
    for (int a = threadIdx.x; a < ACT; a += 256) {
        float av[16];
        #pragma unroll
        for (int r = 0; r < 16; r++) av[r] = lA[(size_t)r * ACT + a];
        #pragma unroll
        for (int o = 0; o < 16; o++) {
            float acc = Wb[(size_t)(ob + o) * ACT + a];
            #pragma unroll
            for (int r = 0; r < 16; r++) acc += lb[o][r] * av[r];
            g_wh[(size_t)(ob + o) * ACT + a] = __float2half_rn(acc);
        }
    }
}

// ---------------- kernel 2: gather active in-features -> fp16 (half2 stores) ----
__global__ void gather_x_kernel(const float* __restrict__ x,
                                const int* __restrict__ in_idx) {
    int n = blockIdx.y;
    int a = (blockIdx.x * blockDim.x + threadIdx.x) * 2;
    int i0 = in_idx[a];
    int i1 = in_idx[a + 1];
    const float* xr = x + (size_t)n * ORIGF;
    __half2 v = __floats2half2_rn(xr[i0], xr[i1]);
    *reinterpret_cast<__half2*>(&g_xh[(size_t)n * ACT + a]) = v;
}

// ---------------- kernel 3: compact list of inactive output columns ----------
// rank of j among inactive cols = j - (#active cols < j); no atomics needed.
__global__ void build_ninv_kernel(const int* __restrict__ out_idx) {
    int j = blockIdx.x * blockDim.x + threadIdx.x;
    if (j >= ORIGF) return;
    int lo = 0, hi = ACT;
    while (lo < hi) { int mid = (lo + hi) >> 1; if (out_idx[mid] < j) lo = mid + 1; else hi = mid; }
    bool active = (lo < ACT && out_idx[lo] == j);
    if (!active) g_ninv[j - lo] = j;
}

// ---------------- kernel 4: fp16 HMMA GEMM + fused zero/bias/scatter --------
// C[m,n] = sum_k A[m,k]*B[n,k]; store C[m,n]+bias[n] at out[m, out_idx[n]].
// Each CTA also zeros its disjoint slice of inactive columns during prologue.
__global__ void __launch_bounds__(256, 2) gemm_kernel(float* __restrict__ out,
                                                      const float* __restrict__ bias,
                                                      const int* __restrict__ oidx) {
    extern __shared__ char smem[];
    const uint32_t sbase = smem_u32(smem);
    const int tid  = threadIdx.x;
    const int wid  = tid >> 5;
    const int lane = tid & 31;
    const int m0 = blockIdx.y * TM;
    const int n0 = blockIdx.x * TN;
    const int wm = (wid & 1) * 64;     // warp M offset within tile
    const int wn = (wid >> 1) * 32;    // warp N offset within tile

    // Per-lane ldmatrix base addresses (kstep 0), swizzled.
    // kstep advance is a pure XOR: addr_k = addr_0 ^ (ks*32).
    uint32_t a_addr[4], b_addr[2];
    {
        int lr = (lane & 7) + 8 * ((lane >> 3) & 1);
        int lk = ((lane >> 4) & 1) * 16;
        #pragma unroll
        for (int i = 0; i < 4; i++) {
            uint32_t row = (uint32_t)(wm + i * 16 + lr);
            a_addr[i] = SWZ(row * 128u + (uint32_t)lk);
        }
        int br = (lane & 7) + 8 * ((lane >> 4) & 1);
        int bk = ((lane >> 3) & 1) * 16;
        #pragma unroll
        for (int j2 = 0; j2 < 2; j2++) {
            uint32_t row = (uint32_t)(wn + j2 * 16 + br);
            b_addr[j2] = SWZ(row * 128u + (uint32_t)bk);
        }
    }

    float acc[4][4][4];
    #pragma unroll
    for (int i = 0; i < 4; i++)
        #pragma unroll
        for (int j = 0; j < 4; j++)
            #pragma unroll
            for (int r = 0; r < 4; r++) acc[i][j][r] = 0.0f;

    // prologue: chunks 0,1 into stages 0,1 (prefetch distance = NST-1 = 2)
    #pragma unroll
    for (int k = 0; k < NST - 1; k++) {
        uint32_t st = sbase + k * STAGE_BYTES;
        issue_loads(st, st + A_STAGE_BYTES, m0, n0, (uint32_t)k * 128u, tid);
        asm volatile("cp.async.commit_group;" ::: "memory");
    }

    // zero this CTA's slice of inactive output columns (hidden under load latency)
    {
        int col = g_ninv[blockIdx.x * 128 + (tid & 127)];
        float* base = out + (size_t)(m0 + (tid >> 7) * 64) * ORIGF + col;
        #pragma unroll
        for (int r = 0; r < 64; r++)
            base[(size_t)r * ORIGF] = 0.0f;
    }

    int s = 0;
    for (int k = 0; k < NCHUNK; k++) {
        asm volatile("cp.async.wait_group 1;" ::: "memory");   // chunk k landed
        __syncthreads();   // all warps past chunk k-1's ldsm -> stage (k+2)%3 free

        // issue chunk k+2 into stage (k+2)%NST BEFORE computing chunk k
        int kn = k + (NST - 1);
        if (kn < NCHUNK) {
            uint32_t st = sbase + (kn % NST) * STAGE_BYTES;
            issue_loads(st, st + A_STAGE_BYTES, m0, n0, (uint32_t)kn * 128u, tid);
        }
        asm volatile("cp.async.commit_group;" ::: "memory");   // empty at tail keeps counts uniform

        const uint32_t sa = sbase + s * STAGE_BYTES;
        const uint32_t sb = sa + A_STAGE_BYTES;
        #pragma unroll
        for (int ks = 0; ks < 4; ks++) {
            const uint32_t kb = (uint32_t)ks * 32u;
            uint32_t a[4][4], b[2][4];
            #pragma unroll
            for (int i = 0; i < 4; i++)  ldsm4(a[i],  sa + (a_addr[i]  ^ kb));
            #pragma unroll
            for (int j2 = 0; j2 < 2; j2++) ldsm4(b[j2], sb + (b_addr[j2] ^ kb));
            #pragma unroll
            for (int i = 0; i < 4; i++)
                #pragma unroll
                for (int j = 0; j < 4; j++)
                    mma16816(acc[i][j], a[i], &b[j >> 1][(j & 1) * 2]);
        }

        s = (s == NST - 1) ? 0 : s + 1;
    }

    // epilogue: fused bias + scatter into final out
    int   cc[4][2];
    float bb2[4][2];
    #pragma unroll
    for (int j = 0; j < 4; j++) {
        int nc = n0 + wn + j * 8 + (lane & 3) * 2;
        cc[j][0]  = oidx[nc];     cc[j][1]  = oidx[nc + 1];
        bb2[j][0] = bias[nc];     bb2[j][1] = bias[nc + 1];
    }
    #pragma unroll
    for (int i = 0; i < 4; i++) {
        int mrow = m0 + wm + i * 16 + (lane >> 2);
        float* r0 = out + (size_t)mrow * ORIGF;
        float* r1 = r0 + (size_t)8 * ORIGF;
        #pragma unroll
        for (int j = 0; j < 4; j++) {
            r0[cc[j][0]] = acc[i][j][0] + bb2[j][0];
            r0[cc[j][1]] = acc[i][j][1] + bb2[j][1];
            r1[cc[j][0]] = acc[i][j][2] + bb2[j][0];
            r1[cc[j][1]] = acc[i][j][3] + bb2[j][1];
        }
    }
}

// ---------------- launch ----------------
extern "C" void kernel_launch(void* const* d_in, const int* in_sizes, int n_in,
                              void* d_out, int out_size) {
    (void)in_sizes; (void)n_in; (void)out_size;
    const float* x    = (const float*)d_in[0];
    const float* Wb   = (const float*)d_in[1];
    const float* bb   = (const float*)d_in[2];
    const float* lA   = (const float*)d_in[3];
    const float* lB   = (const float*)d_in[4];
    const int*   iin  = (const int*)d_in[5];
    const int*   iout = (const int*)d_in[6];
    float* out = (float*)d_out;

    cudaFuncSetAttribute(gemm_kernel,
                         cudaFuncAttributeMaxDynamicSharedMemorySize, GEMM_SMEM);

    build_ninv_kernel<<<ORIGF / 256, 256>>>(iout);
    prep_w_kernel<<<ACT / 16, 256>>>(Wb, lA, lB);
    gather_x_kernel<<<dim3(ACT / 512, NTOK), 256>>>(x, iin);
    gemm_kernel<<<dim3(ACT / TN, NTOK / TM), 256, GEMM_SMEM>>>(out, bb, iout);
}